// round 11
// baseline (speedup 1.0000x reference)
#include <cuda_runtime.h>
#include <math.h>
#include <stdint.h>

#define BB 4
#define NN 4096
#define EPSF 1e-9f

typedef unsigned long long ull;

// ---------------- scratch (device globals; no allocation allowed) ----------------
__device__ __align__(16) float g_qb[BB * NN * 64];    // base q, pre-scaled by 1/sqrt(64)
__device__ __align__(16) float g_kb[BB * NN * 64];    // base k
__device__ __align__(16) float g_qf[BB * NN * 128];   // hedgehog features q
__device__ __align__(16) float g_kf[BB * NN * 128];   // hedgehog features k
__device__ float g_mT[BB * NN];
__device__ float g_sT[BB * NN];
__device__ float g_mP[BB * NN];
__device__ float g_sP[BB * NN];
__device__ float g_rowloss[BB * NN];

// packed fp32x2 FMA (sm_100+ only; ptxas never emits this from C++)
__device__ __forceinline__ ull fma2(ull a, ull b, ull c) {
    ull d;
    asm("fma.rn.f32x2 %0, %1, %2, %3;" : "=l"(d) : "l"(a), "l"(b), "l"(c));
    return d;
}

// ---------------- kernel 1: projections + feature maps ----------------
// side==0: q path (base scale 1/8), side==1: k path (scale 1)
__global__ void __launch_bounds__(256) feat_kernel(
    const float* __restrict__ h,
    const float* __restrict__ Wbase,
    const float* __restrict__ Wmlp,
    const float* __restrict__ bias,
    int side)
{
    __shared__ float sWb[64][65];
    __shared__ float sWm[64][65];
    __shared__ float sb[64];
    __shared__ float sh[4][64];

    float* out_base = side ? g_kb : g_qb;
    float* out_feat = side ? g_kf : g_qf;
    const float base_scale = side ? 1.0f : 0.125f;  // fold 1/sqrt(64) into q

    int tid = threadIdx.x;
    for (int idx = tid; idx < 4096; idx += 256) {
        sWb[idx >> 6][idx & 63] = Wbase[idx];
        sWm[idx >> 6][idx & 63] = Wmlp[idx];
    }
    if (tid < 64) sb[tid] = bias[tid];
    __syncthreads();

    int R0 = blockIdx.x * 128;   // 128 rows per block, 128 blocks -> 16384 rows
    int rr = tid >> 6, e = tid & 63;

    for (int r4 = 0; r4 < 128; r4 += 4) {
        int row = R0 + r4 + rr;
        sh[rr][e] = h[row * 64 + e];
        __syncthreads();
        float accb = 0.f, accm = 0.f;
#pragma unroll
        for (int d0 = 0; d0 < 64; d0++) {
            float hv = sh[rr][d0];
            accb = fmaf(hv, sWb[e][d0], accb);
            accm = fmaf(hv, sWm[e][d0], accm);
        }
        out_base[row * 64 + e] = accb * base_scale;
        float z = accm + sb[e];
        out_feat[row * 128 + e]       = __expf(z);
        out_feat[row * 128 + 64 + e]  = __expf(-z);
        __syncthreads();
    }
}

// ---------------- kernels 2-5: GEMM + softmax passes ----------------
// BM=128 rows/block, BN=64 cols/tile, KC=32 k-chunk. 256 threads = 16(ty) x 16(tx).
// Thread micro-tile: rows ty*8..ty*8+7 (4 f32x2 row-pairs), cols tx+16j (j<4).
// PASS 0: online row max/sum.  PASS 1: write probs.  PASS 2: write probs + KD loss.
template <int D, int PASS>
__global__ void __launch_bounds__(256) attn_kernel(
    const float* __restrict__ true_attn,
    float* __restrict__ outp)
{
    const float* __restrict__ Q = (D == 64) ? g_qb : g_qf;
    const float* __restrict__ K = (D == 64) ? g_kb : g_kf;
    float* rowmax = (D == 64) ? g_mT : g_mP;
    float* rowsum = (D == 64) ? g_sT : g_sP;

    __shared__ __align__(16) float  sA[32][132];   // [k][row], padded
    __shared__ __align__(16) float2 sBd[32][66];   // [k][col], value duplicated (b,b)

    int tid = threadIdx.x;
    int tx = tid & 15, ty = tid >> 4;
    int b = blockIdx.y;
    int row0 = blockIdx.x * 128;
    const float* Qb = Q + ((size_t)(b * NN) + row0) * D;
    const float* Kb = K + (size_t)b * NN * D;

    float m[8], s[8], inv[8], lacc[8];
#pragma unroll
    for (int i = 0; i < 8; i++) { m[i] = -INFINITY; s[i] = 0.f; lacc[i] = 0.f; inv[i] = 0.f; }
    if (PASS != 0) {
#pragma unroll
        for (int i = 0; i < 8; i++) {
            int r = b * NN + row0 + ty * 8 + i;
            m[i]   = rowmax[r];
            inv[i] = 1.0f / rowsum[r];
        }
    }

    for (int ct = 0; ct < NN / 64; ct++) {
        int col0 = ct * 64;
        ull acc2[4][4];
#pragma unroll
        for (int p = 0; p < 4; p++)
#pragma unroll
            for (int j = 0; j < 4; j++) acc2[p][j] = 0ULL;

        for (int ch = 0; ch < D / 32; ch++) {
            const float* Qc = Qb + ch * 32;
            const float* Kc = Kb + (size_t)col0 * D + ch * 32;
#pragma unroll
            for (int l = 0; l < 4; l++) {         // A: 128x32 floats
                int idx = tid + l * 256;
                int row = idx >> 3, kq = (idx & 7) << 2;
                float4 v = *(const float4*)(Qc + row * D + kq);
                sA[kq + 0][row] = v.x; sA[kq + 1][row] = v.y;
                sA[kq + 2][row] = v.z; sA[kq + 3][row] = v.w;
            }
#pragma unroll
            for (int l = 0; l < 2; l++) {         // B: 64x32 floats, duplicated
                int idx = tid + l * 256;
                int c = idx >> 3, kq = (idx & 7) << 2;
                float4 v = *(const float4*)(Kc + c * D + kq);
                sBd[kq + 0][c] = make_float2(v.x, v.x);
                sBd[kq + 1][c] = make_float2(v.y, v.y);
                sBd[kq + 2][c] = make_float2(v.z, v.z);
                sBd[kq + 3][c] = make_float2(v.w, v.w);
            }
            __syncthreads();
#pragma unroll
            for (int k = 0; k < 32; k++) {
                ull av[4], bv[4];
#pragma unroll
                for (int p = 0; p < 4; p++) av[p] = *(const ull*)(&sA[k][ty * 8 + 2 * p]);
#pragma unroll
                for (int j = 0; j < 4; j++) bv[j] = *(const ull*)(&sBd[k][tx + 16 * j]);
#pragma unroll
                for (int p = 0; p < 4; p++)
#pragma unroll
                    for (int j = 0; j < 4; j++)
                        acc2[p][j] = fma2(av[p], bv[j], acc2[p][j]);
            }
            __syncthreads();
        }

        // ---- epilogue on this 128x64 score tile ----
#pragma unroll
        for (int p = 0; p < 4; p++) {
            const int i0 = 2 * p, i1 = 2 * p + 1;
#pragma unroll
            for (int j = 0; j < 4; j++) {
                float2 vv = *(float2*)&acc2[p][j];
                if (PASS == 0) {
                    if (vv.x > m[i0]) { s[i0] = s[i0] * __expf(m[i0] - vv.x) + 1.0f; m[i0] = vv.x; }
                    else               s[i0] += __expf(vv.x - m[i0]);
                    if (vv.y > m[i1]) { s[i1] = s[i1] * __expf(m[i1] - vv.y) + 1.0f; m[i1] = vv.y; }
                    else               s[i1] += __expf(vv.y - m[i1]);
                } else {
                    int c = col0 + tx + 16 * j;
                    size_t ro0 = ((size_t)(b * NN) + row0 + ty * 8 + i0) * NN + c;
                    size_t ro1 = ro0 + NN;
                    float p0 = __expf(vv.x - m[i0]) * inv[i0];
                    float p1 = __expf(vv.y - m[i1]) * inv[i1];
                    outp[ro0] = p0;
                    outp[ro1] = p1;
                    if (PASS == 2) {
                        float t0 = true_attn[ro0];
                        float t1 = true_attn[ro1];
                        lacc[i0] = fmaf(t0, __logf(p0 + EPSF), lacc[i0]);
                        lacc[i1] = fmaf(t1, __logf(p1 + EPSF), lacc[i1]);
                    }
                }
            }
        }
    }

    if (PASS == 0) {
#pragma unroll
        for (int i = 0; i < 8; i++) {
            float mi = m[i];
#pragma unroll
            for (int o = 8; o >= 1; o >>= 1)
                mi = fmaxf(mi, __shfl_xor_sync(0xffffffffu, mi, o));
            float si = s[i] * __expf(m[i] - mi);
#pragma unroll
            for (int o = 8; o >= 1; o >>= 1)
                si += __shfl_xor_sync(0xffffffffu, si, o);
            if (tx == 0) {
                int r = b * NN + row0 + ty * 8 + i;
                rowmax[r] = mi;
                rowsum[r] = si;
            }
        }
    }
    if (PASS == 2) {
#pragma unroll
        for (int i = 0; i < 8; i++) {
            float li = lacc[i];
#pragma unroll
            for (int o = 8; o >= 1; o >>= 1)
                li += __shfl_xor_sync(0xffffffffu, li, o);
            if (tx == 0) g_rowloss[b * NN + row0 + ty * 8 + i] = -li;
        }
    }
}

// ---------------- kernel 6: loss mean ----------------
__global__ void loss_reduce_kernel(float* __restrict__ out)
{
    __shared__ float sm[256];
    int tid = threadIdx.x;
    float a = 0.f;
    for (int i = tid; i < BB * NN; i += 256) a += g_rowloss[i];
    sm[tid] = a;
    __syncthreads();
    for (int o = 128; o > 0; o >>= 1) {
        if (tid < o) sm[tid] += sm[tid + o];
        __syncthreads();
    }
    if (tid == 0) out[0] = sm[0] / (float)(BB * NN);
}

// ---------------- launch ----------------
extern "C" void kernel_launch(void* const* d_in, const int* in_sizes, int n_in,
                              void* d_out, int out_size)
{
    (void)in_sizes; (void)n_in; (void)out_size;
    const float* h   = (const float*)d_in[0];
    const float* Wqm = (const float*)d_in[1];
    const float* bqm = (const float*)d_in[2];
    const float* Wkm = (const float*)d_in[3];
    const float* bkm = (const float*)d_in[4];
    const float* Wqb = (const float*)d_in[5];
    const float* Wkb = (const float*)d_in[6];

    float* out      = (float*)d_out;
    float* out_pred = out + 1;
    float* out_true = out + 1 + (size_t)BB * NN * NN;

    feat_kernel<<<128, 256>>>(h, Wqb, Wqm, bqm, 0);
    feat_kernel<<<128, 256>>>(h, Wkb, Wkm, bkm, 1);

    dim3 grid(NN / 128, BB);
    attn_kernel<64, 0><<<grid, 256>>>(nullptr, nullptr);     // true stats
    attn_kernel<128, 0><<<grid, 256>>>(nullptr, nullptr);    // pred stats
    attn_kernel<64, 1><<<grid, 256>>>(nullptr, out_true);    // write true_attn
    attn_kernel<128, 2><<<grid, 256>>>(out_true, out_pred);  // write pred_attn + loss
    loss_reduce_kernel<<<1, 256>>>(out);
}

// round 12
// speedup vs baseline: 1.0035x; 1.0035x over previous
#include <cuda_runtime.h>
#include <math.h>
#include <stdint.h>

#define BB 4
#define NN 4096
#define EPSF 1e-9f

typedef unsigned long long ull;

// ---------------- scratch (device globals; no allocation allowed) ----------------
__device__ __align__(16) float g_qb[BB * NN * 64];    // base q, pre-scaled by 1/sqrt(64)
__device__ __align__(16) float g_kb[BB * NN * 64];    // base k
__device__ __align__(16) float g_qf[BB * NN * 128];   // hedgehog features q
__device__ __align__(16) float g_kf[BB * NN * 128];   // hedgehog features k
__device__ float g_mT[BB * NN];
__device__ float g_sT[BB * NN];
__device__ float g_mP[BB * NN];
__device__ float g_sP[BB * NN];
__device__ float g_rowloss[BB * NN];

// packed fp32x2 FMA (sm_100+ only; ptxas never emits this from C++)
__device__ __forceinline__ ull fma2(ull a, ull b, ull c) {
    ull d;
    asm("fma.rn.f32x2 %0, %1, %2, %3;" : "=l"(d) : "l"(a), "l"(b), "l"(c));
    return d;
}

// ---------------- kernel 1: projections + feature maps ----------------
// side==0: q path (base scale 1/8), side==1: k path (scale 1)
__global__ void __launch_bounds__(256) feat_kernel(
    const float* __restrict__ h,
    const float* __restrict__ Wbase,
    const float* __restrict__ Wmlp,
    const float* __restrict__ bias,
    int side)
{
    __shared__ float sWb[64][65];
    __shared__ float sWm[64][65];
    __shared__ float sb[64];
    __shared__ float sh[4][64];

    float* out_base = side ? g_kb : g_qb;
    float* out_feat = side ? g_kf : g_qf;
    const float base_scale = side ? 1.0f : 0.125f;  // fold 1/sqrt(64) into q

    int tid = threadIdx.x;
    for (int idx = tid; idx < 4096; idx += 256) {
        sWb[idx >> 6][idx & 63] = Wbase[idx];
        sWm[idx >> 6][idx & 63] = Wmlp[idx];
    }
    if (tid < 64) sb[tid] = bias[tid];
    __syncthreads();

    int R0 = blockIdx.x * 128;   // 128 rows per block, 128 blocks -> 16384 rows
    int rr = tid >> 6, e = tid & 63;

    for (int r4 = 0; r4 < 128; r4 += 4) {
        int row = R0 + r4 + rr;
        sh[rr][e] = h[row * 64 + e];
        __syncthreads();
        float accb = 0.f, accm = 0.f;
#pragma unroll
        for (int d0 = 0; d0 < 64; d0++) {
            float hv = sh[rr][d0];
            accb = fmaf(hv, sWb[e][d0], accb);
            accm = fmaf(hv, sWm[e][d0], accm);
        }
        out_base[row * 64 + e] = accb * base_scale;
        float z = accm + sb[e];
        out_feat[row * 128 + e]       = __expf(z);
        out_feat[row * 128 + 64 + e]  = __expf(-z);
        __syncthreads();
    }
}

// ---------------- kernels 2-5: GEMM + softmax passes ----------------
// BM=128 rows/block, BN=64 cols/tile, KC=32 k-chunk. 256 threads = 16(ty) x 16(tx).
// Thread micro-tile: rows ty*8..ty*8+7 (4 f32x2 row-pairs), cols tx+16j (j<4).
// PASS 0: online row max/sum.  PASS 1: write probs.  PASS 2: write probs + KD loss.
template <int D, int PASS>
__global__ void __launch_bounds__(256) attn_kernel(
    const float* __restrict__ true_attn,
    float* __restrict__ outp)
{
    const float* __restrict__ Q = (D == 64) ? g_qb : g_qf;
    const float* __restrict__ K = (D == 64) ? g_kb : g_kf;
    float* rowmax = (D == 64) ? g_mT : g_mP;
    float* rowsum = (D == 64) ? g_sT : g_sP;

    __shared__ __align__(16) float  sA[32][132];   // [k][row], padded
    __shared__ __align__(16) float2 sBd[32][66];   // [k][col], value duplicated (b,b)

    int tid = threadIdx.x;
    int tx = tid & 15, ty = tid >> 4;
    int b = blockIdx.y;
    int row0 = blockIdx.x * 128;
    const float* Qb = Q + ((size_t)(b * NN) + row0) * D;
    const float* Kb = K + (size_t)b * NN * D;

    float m[8], s[8], inv[8], lacc[8];
#pragma unroll
    for (int i = 0; i < 8; i++) { m[i] = -INFINITY; s[i] = 0.f; lacc[i] = 0.f; inv[i] = 0.f; }
    if (PASS != 0) {
#pragma unroll
        for (int i = 0; i < 8; i++) {
            int r = b * NN + row0 + ty * 8 + i;
            m[i]   = rowmax[r];
            inv[i] = 1.0f / rowsum[r];
        }
    }

    for (int ct = 0; ct < NN / 64; ct++) {
        int col0 = ct * 64;
        ull acc2[4][4];
#pragma unroll
        for (int p = 0; p < 4; p++)
#pragma unroll
            for (int j = 0; j < 4; j++) acc2[p][j] = 0ULL;

        for (int ch = 0; ch < D / 32; ch++) {
            const float* Qc = Qb + ch * 32;
            const float* Kc = Kb + (size_t)col0 * D + ch * 32;
#pragma unroll
            for (int l = 0; l < 4; l++) {         // A: 128x32 floats
                int idx = tid + l * 256;
                int row = idx >> 3, kq = (idx & 7) << 2;
                float4 v = *(const float4*)(Qc + row * D + kq);
                sA[kq + 0][row] = v.x; sA[kq + 1][row] = v.y;
                sA[kq + 2][row] = v.z; sA[kq + 3][row] = v.w;
            }
#pragma unroll
            for (int l = 0; l < 2; l++) {         // B: 64x32 floats, duplicated
                int idx = tid + l * 256;
                int c = idx >> 3, kq = (idx & 7) << 2;
                float4 v = *(const float4*)(Kc + c * D + kq);
                sBd[kq + 0][c] = make_float2(v.x, v.x);
                sBd[kq + 1][c] = make_float2(v.y, v.y);
                sBd[kq + 2][c] = make_float2(v.z, v.z);
                sBd[kq + 3][c] = make_float2(v.w, v.w);
            }
            __syncthreads();
#pragma unroll
            for (int k = 0; k < 32; k++) {
                ull av[4], bv[4];
#pragma unroll
                for (int p = 0; p < 4; p++) av[p] = *(const ull*)(&sA[k][ty * 8 + 2 * p]);
#pragma unroll
                for (int j = 0; j < 4; j++) bv[j] = *(const ull*)(&sBd[k][tx + 16 * j]);
#pragma unroll
                for (int p = 0; p < 4; p++)
#pragma unroll
                    for (int j = 0; j < 4; j++)
                        acc2[p][j] = fma2(av[p], bv[j], acc2[p][j]);
            }
            __syncthreads();
        }

        // ---- epilogue on this 128x64 score tile ----
#pragma unroll
        for (int p = 0; p < 4; p++) {
            const int i0 = 2 * p, i1 = 2 * p + 1;
#pragma unroll
            for (int j = 0; j < 4; j++) {
                float2 vv = *(float2*)&acc2[p][j];
                if (PASS == 0) {
                    if (vv.x > m[i0]) { s[i0] = s[i0] * __expf(m[i0] - vv.x) + 1.0f; m[i0] = vv.x; }
                    else               s[i0] += __expf(vv.x - m[i0]);
                    if (vv.y > m[i1]) { s[i1] = s[i1] * __expf(m[i1] - vv.y) + 1.0f; m[i1] = vv.y; }
                    else               s[i1] += __expf(vv.y - m[i1]);
                } else {
                    int c = col0 + tx + 16 * j;
                    size_t ro0 = ((size_t)(b * NN) + row0 + ty * 8 + i0) * NN + c;
                    size_t ro1 = ro0 + NN;
                    float p0 = __expf(vv.x - m[i0]) * inv[i0];
                    float p1 = __expf(vv.y - m[i1]) * inv[i1];
                    outp[ro0] = p0;
                    outp[ro1] = p1;
                    if (PASS == 2) {
                        float t0 = true_attn[ro0];
                        float t1 = true_attn[ro1];
                        lacc[i0] = fmaf(t0, __logf(p0 + EPSF), lacc[i0]);
                        lacc[i1] = fmaf(t1, __logf(p1 + EPSF), lacc[i1]);
                    }
                }
            }
        }
    }

    if (PASS == 0) {
#pragma unroll
        for (int i = 0; i < 8; i++) {
            float mi = m[i];
#pragma unroll
            for (int o = 8; o >= 1; o >>= 1)
                mi = fmaxf(mi, __shfl_xor_sync(0xffffffffu, mi, o));
            float si = s[i] * __expf(m[i] - mi);
#pragma unroll
            for (int o = 8; o >= 1; o >>= 1)
                si += __shfl_xor_sync(0xffffffffu, si, o);
            if (tx == 0) {
                int r = b * NN + row0 + ty * 8 + i;
                rowmax[r] = mi;
                rowsum[r] = si;
            }
        }
    }
    if (PASS == 2) {
#pragma unroll
        for (int i = 0; i < 8; i++) {
            float li = lacc[i];
#pragma unroll
            for (int o = 8; o >= 1; o >>= 1)
                li += __shfl_xor_sync(0xffffffffu, li, o);
            if (tx == 0) g_rowloss[b * NN + row0 + ty * 8 + i] = -li;
        }
    }
}

// ---------------- kernel 6: loss mean ----------------
__global__ void loss_reduce_kernel(float* __restrict__ out)
{
    __shared__ float sm[256];
    int tid = threadIdx.x;
    float a = 0.f;
    for (int i = tid; i < BB * NN; i += 256) a += g_rowloss[i];
    sm[tid] = a;
    __syncthreads();
    for (int o = 128; o > 0; o >>= 1) {
        if (tid < o) sm[tid] += sm[tid + o];
        __syncthreads();
    }
    if (tid == 0) out[0] = sm[0] / (float)(BB * NN);
}

// ---------------- launch ----------------
extern "C" void kernel_launch(void* const* d_in, const int* in_sizes, int n_in,
                              void* d_out, int out_size)
{
    (void)in_sizes; (void)n_in; (void)out_size;
    const float* h   = (const float*)d_in[0];
    const float* Wqm = (const float*)d_in[1];
    const float* bqm = (const float*)d_in[2];
    const float* Wkm = (const float*)d_in[3];
    const float* bkm = (const float*)d_in[4];
    const float* Wqb = (const float*)d_in[5];
    const float* Wkb = (const float*)d_in[6];

    float* out      = (float*)d_out;
    float* out_pred = out + 1;
    float* out_true = out + 1 + (size_t)BB * NN * NN;

    feat_kernel<<<128, 256>>>(h, Wqb, Wqm, bqm, 0);
    feat_kernel<<<128, 256>>>(h, Wkb, Wkm, bkm, 1);

    dim3 grid(NN / 128, BB);
    attn_kernel<64, 0><<<grid, 256>>>(nullptr, nullptr);     // true stats
    attn_kernel<128, 0><<<grid, 256>>>(nullptr, nullptr);    // pred stats
    attn_kernel<64, 1><<<grid, 256>>>(nullptr, out_true);    // write true_attn
    attn_kernel<128, 2><<<grid, 256>>>(out_true, out_pred);  // write pred_attn + loss
    loss_reduce_kernel<<<1, 256>>>(out);
}